// round 11
// baseline (speedup 1.0000x reference)
#include <cuda_runtime.h>
#include <cuda_bf16.h>
#include <cstdint>

// ---------------- problem constants ----------------
#define B_    8
#define H_    56
#define W_    56
#define C_    192
#define NWH   14            // windows per side (56/4)
#define BW    1568          // total windows
#define MP    1664          // padded window rows = 13 * 128
#define IND   3072          // 4*4*192
#define HID   256
#define NCL   256
#define KSPL  4             // GEMM1 split-K

// ---------------- scratch (__device__ globals, zero-initialized) ----------
__device__ __nv_bfloat16 g_win[MP * IND];        // LN'd windows, bf16
__device__ __nv_bfloat16 g_W1T[HID * IND];       // W1^T  [256][3072]
__device__ __nv_bfloat16 g_W2T[IND * C_];        // W2^T  [3072][192]
__device__ __nv_bfloat16 g_vwT[256 * NCL];       // vote^T [256 rows (192 valid)][256]
__device__ float         g_part[KSPL * MP * HID];// GEMM1 split-K partials
__device__ uint32_t      g_incb[16 * NCL];       // include bits [16 words][256 clauses]
__device__ __nv_bfloat16 g_clb[MP * NCL];        // clauses (0/1) bf16
__device__ __nv_bfloat16 g_logb[MP * C_];        // logits bf16

__device__ __forceinline__ float sigmoidf_(float x) { return 1.0f / (1.0f + __expf(-x)); }

__device__ __forceinline__ uint32_t s2u(const void* p) {
    uint32_t a;
    asm("{ .reg .u64 t; cvta.to.shared.u64 t, %1; cvt.u32.u64 %0, t; }" : "=r"(a) : "l"(p));
    return a;
}
#define CP_ASYNC16(dst, src) \
    asm volatile("cp.async.cg.shared.global [%0], [%1], 16;" :: "r"(dst), "l"(src))
#define CP_COMMIT() asm volatile("cp.async.commit_group;")
#define CP_WAIT(n)  asm volatile("cp.async.wait_group %0;" :: "n"(n))

// ---------------- fused K1: LN+roll+partition  AND  weight prep ---------------
// blocks [0, NB_LN): LayerNorm (8 warps = 8 pixels per block)
// blocks [NB_LN, NB_LN+NB_PREP): flat prep (transposes + include bitpack)
#define NB_LN   3136           // 25088 pixels / 8 warps
#define SEG1 786432            // trW1:  3072*256
#define SEG2 1376256           // +trW2: 192*3072
#define SEG3 1425408           // +trVote: 256*192
#define SEGT 1556480           // +pack_inc: 256*512
#define NB_PREP (SEGT / 256)   // 6080
__global__ void ln_prep_kernel(const float* __restrict__ x,
                               const float* __restrict__ gamma,
                               const float* __restrict__ beta,
                               const float* __restrict__ W1,
                               const float* __restrict__ W2,
                               const float* __restrict__ vw,
                               const float* __restrict__ inc_w) {
    if (blockIdx.x < NB_LN) {
        int gwarp = (blockIdx.x * blockDim.x + threadIdx.x) >> 5;
        int lane  = threadIdx.x & 31;
        const float* xr = x + (size_t)gwarp * C_;
        float v[6];
        float s = 0.f, ss = 0.f;
#pragma unroll
        for (int k = 0; k < 6; k++) {
            v[k] = xr[lane + 32 * k];
            s += v[k]; ss += v[k] * v[k];
        }
#pragma unroll
        for (int o = 16; o > 0; o >>= 1) {
            s  += __shfl_xor_sync(0xffffffffu, s, o);
            ss += __shfl_xor_sync(0xffffffffu, ss, o);
        }
        float mean = s * (1.0f / C_);
        float var  = ss * (1.0f / C_) - mean * mean;
        float inv  = rsqrtf(var + 1e-5f);

        int p = gwarp;
        int w = p % W_;
        int h = (p / W_) % H_;
        int b = p / (H_ * W_);
        int hr = (h + H_ - 2) % H_;
        int wr = (w + W_ - 2) % W_;
        int row  = b * (NWH * NWH) + (hr >> 2) * NWH + (wr >> 2);
        size_t base = (size_t)row * IND + ((hr & 3) * 4 + (wr & 3)) * C_;
#pragma unroll
        for (int k = 0; k < 6; k++) {
            int c = lane + 32 * k;
            g_win[base + c] = __float2bfloat16_rn((v[k] - mean) * inv * gamma[c] + beta[c]);
        }
    } else {
        int t = (blockIdx.x - NB_LN) * blockDim.x + threadIdx.x;
        if (t < SEG1) {                       // [3072][256] -> [256][3072]
            int k = t >> 8, n = t & 255;
            g_W1T[(size_t)n * IND + k] = __float2bfloat16_rn(W1[t]);
        } else if (t < SEG2) {                // [192][3072] -> [3072][192]
            int u = t - SEG1;
            int k = u / IND, n = u % IND;
            g_W2T[(size_t)n * C_ + k] = __float2bfloat16_rn(W2[u]);
        } else if (t < SEG3) {                // [256][192] -> [192(pad256)][256]
            int u = t - SEG2;
            int k = u / C_, n = u % C_;
            g_vwT[(size_t)n * NCL + k] = __float2bfloat16_rn(vw[u]);
        } else {                              // include bits: inc = (inc_w > 0)
            int u  = t - SEG3;
            int cl = u >> 9, j = u & 511;
            bool v = inc_w[(size_t)cl * 512 + j] > 0.0f;
            uint32_t m = __ballot_sync(0xffffffffu, v);
            if ((j & 31) == 0) g_incb[(j >> 5) * NCL + cl] = m;
        }
    }
}

// ---------------- bf16 mma.sync GEMM, 2-stage cp.async pipeline ---------------
// D[m][n] = sum_k A[m][k]*B[n][k];  128x128 tile, BK=32, 8 warps x (64x32).
// EPI 0: GEMM3 fused final epilogue (window reverse + roll + gate + residual)
// EPI 1: acc*scale -> bf16 Cb (guard col < nValid)
// EPI 2: raw fp32 partial -> Cf + z*zStride
template <int EPI>
__global__ void __launch_bounds__(256)
mma_gemm(const __nv_bfloat16* __restrict__ A, int lda,
         const __nv_bfloat16* __restrict__ Bm, int ldb,
         const float* __restrict__ bias, float scale,
         float* __restrict__ Cf, __nv_bfloat16* __restrict__ Cb,
         int ldc, int nValid, int kPerZ, int zStride,
         const float* __restrict__ xres, const float* __restrict__ gate,
         float* __restrict__ out) {
    __shared__ __nv_bfloat16 sA[2][128][40];
    __shared__ __nv_bfloat16 sB[2][128][40];
    int tid = threadIdx.x, wid = tid >> 5, lane = tid & 31;
    int bm = blockIdx.y * 128, bn = blockIdx.x * 128;
    int k0 = blockIdx.z * kPerZ;
    if (EPI == 2) Cf += (size_t)blockIdx.z * zStride;

    int wm = (wid & 1) * 64;
    int wn = (wid >> 1) * 32;

    // staging: 128 rows x 32 cols = 512 16B-chunks per tile; 2 chunk-slots/thread
    int i0 = tid,        r0 = i0 >> 2, c0 = (i0 & 3) * 8;
    int i1 = tid + 256,  r1 = i1 >> 2, c1 = (i1 & 3) * 8;
    const __nv_bfloat16* pA0 = A + (size_t)(bm + r0) * lda + c0;
    const __nv_bfloat16* pA1 = A + (size_t)(bm + r1) * lda + c1;
    const __nv_bfloat16* pB0 = Bm + (size_t)(bn + r0) * ldb + c0;
    const __nv_bfloat16* pB1 = Bm + (size_t)(bn + r1) * ldb + c1;

    float c[4][4][4];
#pragma unroll
    for (int i = 0; i < 4; i++)
#pragma unroll
        for (int j = 0; j < 4; j++)
#pragma unroll
            for (int q = 0; q < 4; q++) c[i][j][q] = 0.f;

    int iters = kPerZ >> 5;
    // prologue: stage 0
    CP_ASYNC16(s2u(&sA[0][r0][c0]), pA0 + k0);
    CP_ASYNC16(s2u(&sA[0][r1][c1]), pA1 + k0);
    CP_ASYNC16(s2u(&sB[0][r0][c0]), pB0 + k0);
    CP_ASYNC16(s2u(&sB[0][r1][c1]), pB1 + k0);
    CP_COMMIT();

    for (int it = 0; it < iters; ++it) {
        if (it + 1 < iters) {
            int s = (it + 1) & 1;
            int kb = k0 + (it + 1) * 32;
            CP_ASYNC16(s2u(&sA[s][r0][c0]), pA0 + kb);
            CP_ASYNC16(s2u(&sA[s][r1][c1]), pA1 + kb);
            CP_ASYNC16(s2u(&sB[s][r0][c0]), pB0 + kb);
            CP_ASYNC16(s2u(&sB[s][r1][c1]), pB1 + kb);
            CP_COMMIT();
            CP_WAIT(1);
        } else {
            CP_WAIT(0);
        }
        __syncthreads();
        int cs = it & 1;
#pragma unroll
        for (int ks = 0; ks < 2; ks++) {
            int kk = ks * 16;
            uint32_t a[4][4], b[4][2];
#pragma unroll
            for (int mi = 0; mi < 4; mi++) {
                uint32_t addr = s2u(&sA[cs][wm + mi * 16 + (lane & 15)][kk + (lane >> 4) * 8]);
                asm volatile("ldmatrix.sync.aligned.m8n8.x4.shared.b16 {%0,%1,%2,%3}, [%4];"
                             : "=r"(a[mi][0]), "=r"(a[mi][1]), "=r"(a[mi][2]), "=r"(a[mi][3])
                             : "r"(addr));
            }
#pragma unroll
            for (int ni = 0; ni < 4; ni++) {
                int l = lane & 15;
                uint32_t addr = s2u(&sB[cs][wn + ni * 8 + (l & 7)][kk + (l >> 3) * 8]);
                asm volatile("ldmatrix.sync.aligned.m8n8.x2.shared.b16 {%0,%1}, [%2];"
                             : "=r"(b[ni][0]), "=r"(b[ni][1]) : "r"(addr));
            }
#pragma unroll
            for (int mi = 0; mi < 4; mi++)
#pragma unroll
                for (int ni = 0; ni < 4; ni++)
                    asm volatile(
                        "mma.sync.aligned.m16n8k16.row.col.f32.bf16.bf16.f32 "
                        "{%0,%1,%2,%3}, {%4,%5,%6,%7}, {%8,%9}, {%0,%1,%2,%3};"
                        : "+f"(c[mi][ni][0]), "+f"(c[mi][ni][1]),
                          "+f"(c[mi][ni][2]), "+f"(c[mi][ni][3])
                        : "r"(a[mi][0]), "r"(a[mi][1]), "r"(a[mi][2]), "r"(a[mi][3]),
                          "r"(b[ni][0]), "r"(b[ni][1]));
        }
        __syncthreads();
    }

    // ---------------- epilogues ----------------
    if (EPI == 0) {
        float g = sigmoidf_(gate[0]);
#pragma unroll
        for (int mi = 0; mi < 4; mi++) {
            int row0 = bm + wm + mi * 16 + (lane >> 2);
#pragma unroll
            for (int rr = 0; rr < 2; rr++) {
                int row = row0 + rr * 8;           // window index
                if (row >= BW) continue;
                int b   = row / (NWH * NWH);
                int r2  = row % (NWH * NWH);
                int wh  = r2 / NWH, ww = r2 % NWH;
#pragma unroll
                for (int ni = 0; ni < 4; ni++) {
                    int col = bn + wn + ni * 8 + (lane & 3) * 2;
                    int wpos = col / C_;
                    int ch   = col - wpos * C_;
                    int hr = wh * 4 + (wpos >> 2);
                    int wr = ww * 4 + (wpos & 3);
                    int h = hr + 2; if (h >= H_) h -= H_;
                    int w = wr + 2; if (w >= W_) w -= W_;
                    size_t pix = ((size_t)(b * H_ + h) * W_ + w) * C_ + ch;
                    float v0 = c[mi][ni][rr * 2 + 0];
                    float v1 = c[mi][ni][rr * 2 + 1];
                    float m0 = sigmoidf_(v0 + bias[col]);
                    float m1 = sigmoidf_(v1 + bias[col + 1]);
                    float2 xv = *(const float2*)(xres + pix);
                    float2 o;
                    o.x = xv.x + g * m0 + (1.0f - g) * sigmoidf_(m0);
                    o.y = xv.y + g * m1 + (1.0f - g) * sigmoidf_(m1);
                    *(float2*)(out + pix) = o;
                }
            }
        }
    } else {
#pragma unroll
        for (int mi = 0; mi < 4; mi++) {
            int row = bm + wm + mi * 16 + (lane >> 2);
#pragma unroll
            for (int ni = 0; ni < 4; ni++) {
                int col = bn + wn + ni * 8 + (lane & 3) * 2;
                float v0 = c[mi][ni][0], v1 = c[mi][ni][1];
                float v2 = c[mi][ni][2], v3 = c[mi][ni][3];
                if (EPI == 1) {
                    if (col < nValid) {
                        *(__nv_bfloat162*)(Cb + (size_t)row * ldc + col) =
                            __floats2bfloat162_rn(v0 * scale, v1 * scale);
                        *(__nv_bfloat162*)(Cb + (size_t)(row + 8) * ldc + col) =
                            __floats2bfloat162_rn(v2 * scale, v3 * scale);
                    }
                } else {
                    *(float2*)(Cf + (size_t)row * ldc + col) = make_float2(v0, v1);
                    *(float2*)(Cf + (size_t)(row + 8) * ldc + col) = make_float2(v2, v3);
                }
            }
        }
    }
}

// ---------------- fused: combine split-K -> literal bits -> clauses ----------
__global__ void combine_clause_kernel(const float* __restrict__ b1,
                                      float* __restrict__ out_cl,
                                      float* __restrict__ out_sum) {
    __shared__ uint32_t sinc[16 * NCL];   // 16 KB: include bits cached per block
    __shared__ uint32_t slit[16];
    __shared__ uint32_t scnt[8];
    int row = blockIdx.x;       // 0..MP-1
    int c   = threadIdx.x;      // 0..255  (feature, then clause)
    // cooperative 16KB load of include bits (coalesced, 16 words per thread)
#pragma unroll
    for (int j = 0; j < 16; j++) sinc[c + j * 256] = g_incb[c + j * 256];
    float s = b1[c];
#pragma unroll
    for (int z = 0; z < KSPL; z++) s += g_part[(size_t)z * MP * HID + (size_t)row * HID + c];
    uint32_t mp = __ballot_sync(0xffffffffu, s > 0.0f);
    uint32_t mn = __ballot_sync(0xffffffffu, s < 0.0f);
    if ((c & 31) == 0) {
        slit[c >> 5]       = mp;
        slit[8 + (c >> 5)] = mn;
    }
    __syncthreads();
    uint32_t viol = 0;
#pragma unroll
    for (int i = 0; i < 16; i++) viol |= sinc[i * NCL + c] & ~slit[i];
    float cv = (viol == 0u) ? 1.0f : 0.0f;
    g_clb[(size_t)row * NCL + c] = __float2bfloat16_rn(cv);
    if (row < BW) out_cl[(size_t)row * NCL + c] = cv;
    // summary = popcount of clause bits / 256
    uint32_t cm = __ballot_sync(0xffffffffu, viol == 0u);
    if ((c & 31) == 0) scnt[c >> 5] = (uint32_t)__popc(cm);
    __syncthreads();
    if (c == 0 && row < BW) {
        uint32_t tot = 0;
#pragma unroll
        for (int i = 0; i < 8; i++) tot += scnt[i];
        out_sum[row] = (float)tot * (1.0f / NCL);
    }
}

// ---------------- host launcher -----------------------------------------------
static void* sym_addr(const void* sym) {
    void* p = nullptr;
    cudaGetSymbolAddress(&p, sym);
    return p;
}

extern "C" void kernel_launch(void* const* d_in, const int* in_sizes, int n_in,
                              void* d_out, int out_size) {
    const float* x      = (const float*)d_in[0];
    const float* gamma  = (const float*)d_in[1];
    const float* beta   = (const float*)d_in[2];
    const float* W1     = (const float*)d_in[3];
    const float* b1     = (const float*)d_in[4];
    const float* inc_w  = (const float*)d_in[5];
    const float* vote_w = (const float*)d_in[6];
    const float* W2     = (const float*)d_in[7];
    const float* b2     = (const float*)d_in[8];
    const float* gate   = (const float*)d_in[9];

    float* out     = (float*)d_out;
    float* out_cl  = out + (size_t)B_ * H_ * W_ * C_;
    float* out_sum = out_cl + (size_t)BW * NCL;

    __nv_bfloat16* p_win  = (__nv_bfloat16*)sym_addr(g_win);
    __nv_bfloat16* p_W1T  = (__nv_bfloat16*)sym_addr(g_W1T);
    __nv_bfloat16* p_W2T  = (__nv_bfloat16*)sym_addr(g_W2T);
    __nv_bfloat16* p_vwT  = (__nv_bfloat16*)sym_addr(g_vwT);
    __nv_bfloat16* p_clb  = (__nv_bfloat16*)sym_addr(g_clb);
    __nv_bfloat16* p_logb = (__nv_bfloat16*)sym_addr(g_logb);
    float*         p_part = (float*)sym_addr(g_part);

    // 1) fused: LN + roll + partition  AND  weight transposes + include bitpack
    ln_prep_kernel<<<NB_LN + NB_PREP, 256>>>(x, gamma, beta, W1, W2, vote_w, inc_w);
    // 2) GEMM1 (split-K=4): partials = win @ W1
    mma_gemm<2><<<dim3(2, 13, KSPL), 256>>>(p_win, IND, p_W1T, IND, nullptr, 0.f,
                                            p_part, nullptr, HID, HID, IND / KSPL, MP * HID,
                                            nullptr, nullptr, nullptr);
    // 3) combine partials -> literal bits -> clause bits + outputs
    combine_clause_kernel<<<MP, 256>>>(b1, out_cl, out_sum);
    // 4) GEMM2: logits = clauses @ vote_w / 16 -> bf16
    mma_gemm<1><<<dim3(2, 13, 1), 256>>>(p_clb, NCL, p_vwT, NCL, nullptr, 0.0625f,
                                         nullptr, p_logb, C_, C_, NCL, 0,
                                         nullptr, nullptr, nullptr);
    // 5) GEMM3 + fused final: out = x + blend(sigmoid(logits @ W2 + b2))
    mma_gemm<0><<<dim3(24, 13, 1), 256>>>(p_logb, C_, p_W2T, C_, b2, 0.f,
                                          nullptr, nullptr, IND, IND, C_, 0,
                                          x, gate, out);
}

// round 14
// speedup vs baseline: 1.1392x; 1.1392x over previous
#include <cuda_runtime.h>
#include <cuda_bf16.h>
#include <cstdint>

// ---------------- problem constants ----------------
#define B_    8
#define H_    56
#define W_    56
#define C_    192
#define NWH   14            // windows per side (56/4)
#define BW    1568          // total windows
#define MP    1664          // padded window rows = 13 * 128
#define IND   3072          // 4*4*192
#define HID   256
#define NCL   256
#define KSPL  4             // GEMM1 split-K

// ---------------- scratch (__device__ globals, zero-initialized) ----------
__device__ __nv_bfloat16 g_win[MP * IND];        // LN'd windows, bf16
__device__ __nv_bfloat16 g_W1T[HID * IND];       // W1^T  [256][3072]
__device__ __nv_bfloat16 g_W2T[IND * C_];        // W2^T  [3072][192]
__device__ float         g_part[KSPL * MP * HID];// GEMM1 split-K partials
__device__ uint32_t      g_incb[16 * NCL];       // include bits [16 words][256 clauses]
__device__ __nv_bfloat16 g_logb[MP * C_];        // logits bf16

__device__ __forceinline__ float sigmoidf_(float x) { return 1.0f / (1.0f + __expf(-x)); }

__device__ __forceinline__ uint32_t s2u(const void* p) {
    uint32_t a;
    asm("{ .reg .u64 t; cvta.to.shared.u64 t, %1; cvt.u32.u64 %0, t; }" : "=r"(a) : "l"(p));
    return a;
}
#define CP_ASYNC16(dst, src) \
    asm volatile("cp.async.cg.shared.global [%0], [%1], 16;" :: "r"(dst), "l"(src))
#define CP_COMMIT() asm volatile("cp.async.commit_group;")
#define CP_WAIT(n)  asm volatile("cp.async.wait_group %0;" :: "n"(n))

// ---------------- fused K1: LN+roll+partition  AND  weight prep ---------------
// blocks [0, NB_LN): LayerNorm (8 warps = 8 pixels per block)
// blocks [NB_LN, NB_LN+NB_PREP): flat prep (W1^T, W2^T, include bitpack)
#define NB_LN   3136           // 25088 pixels / 8 warps
#define SEG1 786432            // trW1:  3072*256
#define SEG2 1376256           // +trW2: 192*3072
#define SEGT 1507328           // +pack_inc: 256*512
#define NB_PREP (SEGT / 256)   // 5888
__global__ void ln_prep_kernel(const float* __restrict__ x,
                               const float* __restrict__ gamma,
                               const float* __restrict__ beta,
                               const float* __restrict__ W1,
                               const float* __restrict__ W2,
                               const float* __restrict__ inc_w) {
    if (blockIdx.x < NB_LN) {
        int gwarp = (blockIdx.x * blockDim.x + threadIdx.x) >> 5;
        int lane  = threadIdx.x & 31;
        const float* xr = x + (size_t)gwarp * C_;
        float v[6];
        float s = 0.f, ss = 0.f;
#pragma unroll
        for (int k = 0; k < 6; k++) {
            v[k] = xr[lane + 32 * k];
            s += v[k]; ss += v[k] * v[k];
        }
#pragma unroll
        for (int o = 16; o > 0; o >>= 1) {
            s  += __shfl_xor_sync(0xffffffffu, s, o);
            ss += __shfl_xor_sync(0xffffffffu, ss, o);
        }
        float mean = s * (1.0f / C_);
        float var  = ss * (1.0f / C_) - mean * mean;
        float inv  = rsqrtf(var + 1e-5f);

        int p = gwarp;
        int w = p % W_;
        int h = (p / W_) % H_;
        int b = p / (H_ * W_);
        int hr = (h + H_ - 2) % H_;
        int wr = (w + W_ - 2) % W_;
        int row  = b * (NWH * NWH) + (hr >> 2) * NWH + (wr >> 2);
        size_t base = (size_t)row * IND + ((hr & 3) * 4 + (wr & 3)) * C_;
#pragma unroll
        for (int k = 0; k < 6; k++) {
            int c = lane + 32 * k;
            g_win[base + c] = __float2bfloat16_rn((v[k] - mean) * inv * gamma[c] + beta[c]);
        }
    } else {
        int t = (blockIdx.x - NB_LN) * blockDim.x + threadIdx.x;
        if (t < SEG1) {                       // [3072][256] -> [256][3072]
            int k = t >> 8, n = t & 255;
            g_W1T[(size_t)n * IND + k] = __float2bfloat16_rn(W1[t]);
        } else if (t < SEG2) {                // [192][3072] -> [3072][192]
            int u = t - SEG1;
            int k = u / IND, n = u % IND;
            g_W2T[(size_t)n * C_ + k] = __float2bfloat16_rn(W2[u]);
        } else {                              // include bits: inc = (inc_w > 0)
            int u  = t - SEG2;
            int cl = u >> 9, j = u & 511;
            bool v = inc_w[(size_t)cl * 512 + j] > 0.0f;
            uint32_t m = __ballot_sync(0xffffffffu, v);
            if ((j & 31) == 0) g_incb[(j >> 5) * NCL + cl] = m;
        }
    }
}

// ---------------- bf16 mma.sync GEMM, 2-stage cp.async pipeline ---------------
// D[m][n] = sum_k A[m][k]*B[n][k];  128x128 tile, BK=32, 8 warps x (64x32).
// EPI 0: GEMM3 fused final epilogue (window reverse + roll + gate + residual)
// EPI 2: raw fp32 partial -> Cf + z*zStride
template <int EPI>
__global__ void __launch_bounds__(256)
mma_gemm(const __nv_bfloat16* __restrict__ A, int lda,
         const __nv_bfloat16* __restrict__ Bm, int ldb,
         const float* __restrict__ bias,
         float* __restrict__ Cf, int ldc, int kPerZ, int zStride,
         const float* __restrict__ xres, const float* __restrict__ gate,
         float* __restrict__ out) {
    __shared__ __nv_bfloat16 sA[2][128][40];
    __shared__ __nv_bfloat16 sB[2][128][40];
    int tid = threadIdx.x, wid = tid >> 5, lane = tid & 31;
    int bm = blockIdx.y * 128, bn = blockIdx.x * 128;
    int k0 = blockIdx.z * kPerZ;
    if (EPI == 2) Cf += (size_t)blockIdx.z * zStride;

    int wm = (wid & 1) * 64;
    int wn = (wid >> 1) * 32;

    // staging: 128 rows x 32 cols = 512 16B-chunks per tile; 2 chunk-slots/thread
    int i0 = tid,        r0 = i0 >> 2, c0 = (i0 & 3) * 8;
    int i1 = tid + 256,  r1 = i1 >> 2, c1 = (i1 & 3) * 8;
    const __nv_bfloat16* pA0 = A + (size_t)(bm + r0) * lda + c0;
    const __nv_bfloat16* pA1 = A + (size_t)(bm + r1) * lda + c1;
    const __nv_bfloat16* pB0 = Bm + (size_t)(bn + r0) * ldb + c0;
    const __nv_bfloat16* pB1 = Bm + (size_t)(bn + r1) * ldb + c1;

    float c[4][4][4];
#pragma unroll
    for (int i = 0; i < 4; i++)
#pragma unroll
        for (int j = 0; j < 4; j++)
#pragma unroll
            for (int q = 0; q < 4; q++) c[i][j][q] = 0.f;

    int iters = kPerZ >> 5;
    // prologue: stage 0
    CP_ASYNC16(s2u(&sA[0][r0][c0]), pA0 + k0);
    CP_ASYNC16(s2u(&sA[0][r1][c1]), pA1 + k0);
    CP_ASYNC16(s2u(&sB[0][r0][c0]), pB0 + k0);
    CP_ASYNC16(s2u(&sB[0][r1][c1]), pB1 + k0);
    CP_COMMIT();

    for (int it = 0; it < iters; ++it) {
        if (it + 1 < iters) {
            int s = (it + 1) & 1;
            int kb = k0 + (it + 1) * 32;
            CP_ASYNC16(s2u(&sA[s][r0][c0]), pA0 + kb);
            CP_ASYNC16(s2u(&sA[s][r1][c1]), pA1 + kb);
            CP_ASYNC16(s2u(&sB[s][r0][c0]), pB0 + kb);
            CP_ASYNC16(s2u(&sB[s][r1][c1]), pB1 + kb);
            CP_COMMIT();
            CP_WAIT(1);
        } else {
            CP_WAIT(0);
        }
        __syncthreads();
        int cs = it & 1;
#pragma unroll
        for (int ks = 0; ks < 2; ks++) {
            int kk = ks * 16;
            uint32_t a[4][4], b[4][2];
#pragma unroll
            for (int mi = 0; mi < 4; mi++) {
                uint32_t addr = s2u(&sA[cs][wm + mi * 16 + (lane & 15)][kk + (lane >> 4) * 8]);
                asm volatile("ldmatrix.sync.aligned.m8n8.x4.shared.b16 {%0,%1,%2,%3}, [%4];"
                             : "=r"(a[mi][0]), "=r"(a[mi][1]), "=r"(a[mi][2]), "=r"(a[mi][3])
                             : "r"(addr));
            }
#pragma unroll
            for (int ni = 0; ni < 4; ni++) {
                int l = lane & 15;
                uint32_t addr = s2u(&sB[cs][wn + ni * 8 + (l & 7)][kk + (l >> 3) * 8]);
                asm volatile("ldmatrix.sync.aligned.m8n8.x2.shared.b16 {%0,%1}, [%2];"
                             : "=r"(b[ni][0]), "=r"(b[ni][1]) : "r"(addr));
            }
#pragma unroll
            for (int mi = 0; mi < 4; mi++)
#pragma unroll
                for (int ni = 0; ni < 4; ni++)
                    asm volatile(
                        "mma.sync.aligned.m16n8k16.row.col.f32.bf16.bf16.f32 "
                        "{%0,%1,%2,%3}, {%4,%5,%6,%7}, {%8,%9}, {%0,%1,%2,%3};"
                        : "+f"(c[mi][ni][0]), "+f"(c[mi][ni][1]),
                          "+f"(c[mi][ni][2]), "+f"(c[mi][ni][3])
                        : "r"(a[mi][0]), "r"(a[mi][1]), "r"(a[mi][2]), "r"(a[mi][3]),
                          "r"(b[ni][0]), "r"(b[ni][1]));
        }
        __syncthreads();
    }

    // ---------------- epilogues ----------------
    if (EPI == 0) {
        float g = sigmoidf_(gate[0]);
#pragma unroll
        for (int mi = 0; mi < 4; mi++) {
            int row0 = bm + wm + mi * 16 + (lane >> 2);
#pragma unroll
            for (int rr = 0; rr < 2; rr++) {
                int row = row0 + rr * 8;           // window index
                if (row >= BW) continue;
                int b   = row / (NWH * NWH);
                int r2  = row % (NWH * NWH);
                int wh  = r2 / NWH, ww = r2 % NWH;
#pragma unroll
                for (int ni = 0; ni < 4; ni++) {
                    int col = bn + wn + ni * 8 + (lane & 3) * 2;
                    int wpos = col / C_;
                    int ch   = col - wpos * C_;
                    int hr = wh * 4 + (wpos >> 2);
                    int wr = ww * 4 + (wpos & 3);
                    int h = hr + 2; if (h >= H_) h -= H_;
                    int w = wr + 2; if (w >= W_) w -= W_;
                    size_t pix = ((size_t)(b * H_ + h) * W_ + w) * C_ + ch;
                    float v0 = c[mi][ni][rr * 2 + 0];
                    float v1 = c[mi][ni][rr * 2 + 1];
                    float m0 = sigmoidf_(v0 + bias[col]);
                    float m1 = sigmoidf_(v1 + bias[col + 1]);
                    float2 xv = *(const float2*)(xres + pix);
                    float2 o;
                    o.x = xv.x + g * m0 + (1.0f - g) * sigmoidf_(m0);
                    o.y = xv.y + g * m1 + (1.0f - g) * sigmoidf_(m1);
                    *(float2*)(out + pix) = o;
                }
            }
        }
    } else {
#pragma unroll
        for (int mi = 0; mi < 4; mi++) {
            int row = bm + wm + mi * 16 + (lane >> 2);
#pragma unroll
            for (int ni = 0; ni < 4; ni++) {
                int col = bn + wn + ni * 8 + (lane & 3) * 2;
                *(float2*)(Cf + (size_t)row * ldc + col) =
                    make_float2(c[mi][ni][0], c[mi][ni][1]);
                *(float2*)(Cf + (size_t)(row + 8) * ldc + col) =
                    make_float2(c[mi][ni][2], c[mi][ni][3]);
            }
        }
    }
}

// ------- fused: combine split-K -> clause bits -> outputs -> sparse logits -----
// logits[w,n] = (1/16) * sum over active clauses of vote_w[cl][n]
__global__ void combine_clause_kernel(const float* __restrict__ b1,
                                      const float* __restrict__ vote_w,
                                      float* __restrict__ out_cl,
                                      float* __restrict__ out_sum) {
    __shared__ uint32_t slit[16];
    __shared__ int      swbase[8];
    __shared__ int      scount;
    __shared__ uint16_t sact[256];
    int row  = blockIdx.x;       // 0..MP-1
    int c    = threadIdx.x;      // 0..255  (feature, then clause)
    int wid  = c >> 5, lane = c & 31;
    if (c == 0) scount = 0;
    float s = b1[c];
#pragma unroll
    for (int z = 0; z < KSPL; z++) s += g_part[(size_t)z * MP * HID + (size_t)row * HID + c];
    uint32_t mp = __ballot_sync(0xffffffffu, s > 0.0f);
    uint32_t mn = __ballot_sync(0xffffffffu, s < 0.0f);
    if ((c & 31) == 0) {
        slit[c >> 5]       = mp;
        slit[8 + (c >> 5)] = mn;
    }
    __syncthreads();
    uint32_t viol = 0;
#pragma unroll
    for (int i = 0; i < 16; i++) viol |= g_incb[i * NCL + c] & ~slit[i];
    bool act = (viol == 0u);
    if (row < BW) out_cl[(size_t)row * NCL + c] = act ? 1.0f : 0.0f;
    // compact active clause indices into sact[]
    uint32_t cm = __ballot_sync(0xffffffffu, act);
    if (lane == 0) swbase[wid] = atomicAdd(&scount, __popc(cm));
    __syncwarp();
    if (act) {
        int pos = swbase[wid] + __popc(cm & ((1u << lane) - 1u));
        sact[pos] = (uint16_t)c;
    }
    __syncthreads();
    int total = scount;
    if (c == 0 && row < BW) out_sum[row] = (float)total * (1.0f / NCL);
    // sparse logits: sum active vote_w rows (coalesced across n)
    if (c < C_) {
        float acc = 0.f;
        for (int i = 0; i < total; i++)
            acc += vote_w[(size_t)sact[i] * C_ + c];
        g_logb[(size_t)row * C_ + c] = __float2bfloat16_rn(acc * 0.0625f);
    }
}

// ---------------- host launcher -----------------------------------------------
static void* sym_addr(const void* sym) {
    void* p = nullptr;
    cudaGetSymbolAddress(&p, sym);
    return p;
}

extern "C" void kernel_launch(void* const* d_in, const int* in_sizes, int n_in,
                              void* d_out, int out_size) {
    const float* x      = (const float*)d_in[0];
    const float* gamma  = (const float*)d_in[1];
    const float* beta   = (const float*)d_in[2];
    const float* W1     = (const float*)d_in[3];
    const float* b1     = (const float*)d_in[4];
    const float* inc_w  = (const float*)d_in[5];
    const float* vote_w = (const float*)d_in[6];
    const float* W2     = (const float*)d_in[7];
    const float* b2     = (const float*)d_in[8];
    const float* gate   = (const float*)d_in[9];

    float* out     = (float*)d_out;
    float* out_cl  = out + (size_t)B_ * H_ * W_ * C_;
    float* out_sum = out_cl + (size_t)BW * NCL;

    __nv_bfloat16* p_win  = (__nv_bfloat16*)sym_addr(g_win);
    __nv_bfloat16* p_W1T  = (__nv_bfloat16*)sym_addr(g_W1T);
    __nv_bfloat16* p_W2T  = (__nv_bfloat16*)sym_addr(g_W2T);
    __nv_bfloat16* p_logb = (__nv_bfloat16*)sym_addr(g_logb);
    float*         p_part = (float*)sym_addr(g_part);

    // 1) fused: LN + roll + partition  AND  weight transposes + include bitpack
    ln_prep_kernel<<<NB_LN + NB_PREP, 256>>>(x, gamma, beta, W1, W2, inc_w);
    // 2) GEMM1 (split-K=4): partials = win @ W1
    mma_gemm<2><<<dim3(2, 13, KSPL), 256>>>(p_win, IND, p_W1T, IND, nullptr,
                                            p_part, HID, IND / KSPL, MP * HID,
                                            nullptr, nullptr, nullptr);
    // 3) combine partials -> clause bits + outputs + sparse logits (GEMM2 folded in)
    combine_clause_kernel<<<MP, 256>>>(b1, vote_w, out_cl, out_sum);
    // 4) GEMM3 + fused final: out = x + blend(sigmoid(logits @ W2 + b2))
    mma_gemm<0><<<dim3(24, 13, 1), 256>>>(p_logb, C_, p_W2T, C_, b2,
                                          nullptr, IND, C_, 0,
                                          x, gate, out);
}

// round 15
// speedup vs baseline: 1.1955x; 1.0494x over previous
#include <cuda_runtime.h>
#include <cuda_bf16.h>
#include <cstdint>

// ---------------- problem constants ----------------
#define B_    8
#define H_    56
#define W_    56
#define C_    192
#define NWH   14            // windows per side (56/4)
#define BW    1568          // total windows
#define MP    1664          // padded window rows = 13 * 128
#define IND   3072          // 4*4*192
#define HID   256
#define NCL   256
#define KSPL  4             // GEMM1 split-K

// ---------------- scratch (__device__ globals, zero-initialized) ----------
__device__ __nv_bfloat16 g_win[MP * IND];        // LN'd windows, bf16
__device__ __nv_bfloat16 g_W1T[HID * IND];       // W1^T  [256][3072]
__device__ __nv_bfloat16 g_W2T[IND * C_];        // W2^T  [3072][192]
__device__ float         g_part[KSPL * MP * HID];// GEMM1 split-K partials
__device__ uint32_t      g_incb[16 * NCL];       // include bits [16 words][256 clauses]
__device__ __nv_bfloat16 g_logb[MP * C_];        // logits bf16

__device__ __forceinline__ float sigmoidf_(float x) { return 1.0f / (1.0f + __expf(-x)); }

__device__ __forceinline__ uint32_t s2u(const void* p) {
    uint32_t a;
    asm("{ .reg .u64 t; cvta.to.shared.u64 t, %1; cvt.u32.u64 %0, t; }" : "=r"(a) : "l"(p));
    return a;
}
#define CP_ASYNC16(dst, src) \
    asm volatile("cp.async.cg.shared.global [%0], [%1], 16;" :: "r"(dst), "l"(src))
#define CP_COMMIT() asm volatile("cp.async.commit_group;")
#define CP_WAIT(n)  asm volatile("cp.async.wait_group %0;" :: "n"(n))

// ---------------- fused K1: LN+roll+partition  AND  weight prep ---------------
#define NB_LN   3136           // 25088 pixels / 8 warps
#define SEG1 786432            // trW1:  3072*256
#define SEG2 1376256           // +trW2: 192*3072
#define SEGT 1507328           // +pack_inc: 256*512
#define NB_PREP (SEGT / 256)   // 5888
__global__ void ln_prep_kernel(const float* __restrict__ x,
                               const float* __restrict__ gamma,
                               const float* __restrict__ beta,
                               const float* __restrict__ W1,
                               const float* __restrict__ W2,
                               const float* __restrict__ inc_w) {
    if (blockIdx.x < NB_LN) {
        int gwarp = (blockIdx.x * blockDim.x + threadIdx.x) >> 5;
        int lane  = threadIdx.x & 31;
        const float* xr = x + (size_t)gwarp * C_;
        float v[6];
        float s = 0.f, ss = 0.f;
#pragma unroll
        for (int k = 0; k < 6; k++) {
            v[k] = xr[lane + 32 * k];
            s += v[k]; ss += v[k] * v[k];
        }
#pragma unroll
        for (int o = 16; o > 0; o >>= 1) {
            s  += __shfl_xor_sync(0xffffffffu, s, o);
            ss += __shfl_xor_sync(0xffffffffu, ss, o);
        }
        float mean = s * (1.0f / C_);
        float var  = ss * (1.0f / C_) - mean * mean;
        float inv  = rsqrtf(var + 1e-5f);

        int p = gwarp;
        int w = p % W_;
        int h = (p / W_) % H_;
        int b = p / (H_ * W_);
        int hr = (h + H_ - 2) % H_;
        int wr = (w + W_ - 2) % W_;
        int row  = b * (NWH * NWH) + (hr >> 2) * NWH + (wr >> 2);
        size_t base = (size_t)row * IND + ((hr & 3) * 4 + (wr & 3)) * C_;
#pragma unroll
        for (int k = 0; k < 6; k++) {
            int c = lane + 32 * k;
            g_win[base + c] = __float2bfloat16_rn((v[k] - mean) * inv * gamma[c] + beta[c]);
        }
    } else {
        int t = (blockIdx.x - NB_LN) * blockDim.x + threadIdx.x;
        if (t < SEG1) {                       // [3072][256] -> [256][3072]
            int k = t >> 8, n = t & 255;
            g_W1T[(size_t)n * IND + k] = __float2bfloat16_rn(W1[t]);
        } else if (t < SEG2) {                // [192][3072] -> [3072][192]
            int u = t - SEG1;
            int k = u / IND, n = u % IND;
            g_W2T[(size_t)n * C_ + k] = __float2bfloat16_rn(W2[u]);
        } else {                              // include bits: inc = (inc_w > 0)
            int u  = t - SEG2;
            int cl = u >> 9, j = u & 511;
            bool v = inc_w[(size_t)cl * 512 + j] > 0.0f;
            uint32_t m = __ballot_sync(0xffffffffu, v);
            if ((j & 31) == 0) g_incb[(j >> 5) * NCL + cl] = m;
        }
    }
}

// ---------------- GEMM1: bf16 mma.sync, 128x128 tile, 2-stage cp.async --------
// raw fp32 partial -> Cf + z*zStride
__global__ void __launch_bounds__(256)
mma_gemm1(const __nv_bfloat16* __restrict__ A, int lda,
          const __nv_bfloat16* __restrict__ Bm, int ldb,
          float* __restrict__ Cf, int ldc, int kPerZ, int zStride) {
    __shared__ __nv_bfloat16 sA[2][128][40];
    __shared__ __nv_bfloat16 sB[2][128][40];
    int tid = threadIdx.x, wid = tid >> 5, lane = tid & 31;
    int bm = blockIdx.y * 128, bn = blockIdx.x * 128;
    int k0 = blockIdx.z * kPerZ;
    Cf += (size_t)blockIdx.z * zStride;

    int wm = (wid & 1) * 64;
    int wn = (wid >> 1) * 32;

    int i0 = tid,        r0 = i0 >> 2, c0 = (i0 & 3) * 8;
    int i1 = tid + 256,  r1 = i1 >> 2, c1 = (i1 & 3) * 8;
    const __nv_bfloat16* pA0 = A + (size_t)(bm + r0) * lda + c0;
    const __nv_bfloat16* pA1 = A + (size_t)(bm + r1) * lda + c1;
    const __nv_bfloat16* pB0 = Bm + (size_t)(bn + r0) * ldb + c0;
    const __nv_bfloat16* pB1 = Bm + (size_t)(bn + r1) * ldb + c1;

    float c[4][4][4];
#pragma unroll
    for (int i = 0; i < 4; i++)
#pragma unroll
        for (int j = 0; j < 4; j++)
#pragma unroll
            for (int q = 0; q < 4; q++) c[i][j][q] = 0.f;

    int iters = kPerZ >> 5;
    CP_ASYNC16(s2u(&sA[0][r0][c0]), pA0 + k0);
    CP_ASYNC16(s2u(&sA[0][r1][c1]), pA1 + k0);
    CP_ASYNC16(s2u(&sB[0][r0][c0]), pB0 + k0);
    CP_ASYNC16(s2u(&sB[0][r1][c1]), pB1 + k0);
    CP_COMMIT();

    for (int it = 0; it < iters; ++it) {
        if (it + 1 < iters) {
            int s = (it + 1) & 1;
            int kb = k0 + (it + 1) * 32;
            CP_ASYNC16(s2u(&sA[s][r0][c0]), pA0 + kb);
            CP_ASYNC16(s2u(&sA[s][r1][c1]), pA1 + kb);
            CP_ASYNC16(s2u(&sB[s][r0][c0]), pB0 + kb);
            CP_ASYNC16(s2u(&sB[s][r1][c1]), pB1 + kb);
            CP_COMMIT();
            CP_WAIT(1);
        } else {
            CP_WAIT(0);
        }
        __syncthreads();
        int cs = it & 1;
#pragma unroll
        for (int ks = 0; ks < 2; ks++) {
            int kk = ks * 16;
            uint32_t a[4][4], b[4][2];
#pragma unroll
            for (int mi = 0; mi < 4; mi++) {
                uint32_t addr = s2u(&sA[cs][wm + mi * 16 + (lane & 15)][kk + (lane >> 4) * 8]);
                asm volatile("ldmatrix.sync.aligned.m8n8.x4.shared.b16 {%0,%1,%2,%3}, [%4];"
                             : "=r"(a[mi][0]), "=r"(a[mi][1]), "=r"(a[mi][2]), "=r"(a[mi][3])
                             : "r"(addr));
            }
#pragma unroll
            for (int ni = 0; ni < 4; ni++) {
                int l = lane & 15;
                uint32_t addr = s2u(&sB[cs][wn + ni * 8 + (l & 7)][kk + (l >> 3) * 8]);
                asm volatile("ldmatrix.sync.aligned.m8n8.x2.shared.b16 {%0,%1}, [%2];"
                             : "=r"(b[ni][0]), "=r"(b[ni][1]) : "r"(addr));
            }
#pragma unroll
            for (int mi = 0; mi < 4; mi++)
#pragma unroll
                for (int ni = 0; ni < 4; ni++)
                    asm volatile(
                        "mma.sync.aligned.m16n8k16.row.col.f32.bf16.bf16.f32 "
                        "{%0,%1,%2,%3}, {%4,%5,%6,%7}, {%8,%9}, {%0,%1,%2,%3};"
                        : "+f"(c[mi][ni][0]), "+f"(c[mi][ni][1]),
                          "+f"(c[mi][ni][2]), "+f"(c[mi][ni][3])
                        : "r"(a[mi][0]), "r"(a[mi][1]), "r"(a[mi][2]), "r"(a[mi][3]),
                          "r"(b[ni][0]), "r"(b[ni][1]));
        }
        __syncthreads();
    }

#pragma unroll
    for (int mi = 0; mi < 4; mi++) {
        int row = bm + wm + mi * 16 + (lane >> 2);
#pragma unroll
        for (int ni = 0; ni < 4; ni++) {
            int col = bn + wn + ni * 8 + (lane & 3) * 2;
            *(float2*)(Cf + (size_t)row * ldc + col) =
                make_float2(c[mi][ni][0], c[mi][ni][1]);
            *(float2*)(Cf + (size_t)(row + 8) * ldc + col) =
                make_float2(c[mi][ni][2], c[mi][ni][3]);
        }
    }
}

// ---------------- GEMM3 + fused final: 64x64 tile, full K=192 in 2 phases -----
// out[pix,ch] = x + g*m + (1-g)*sigmoid(m), m = sigmoid(logits@W2 + b2)
__global__ void __launch_bounds__(128)
gemm3_final(const __nv_bfloat16* __restrict__ A,   // g_logb [MP][192]
            const __nv_bfloat16* __restrict__ Bm,  // g_W2T [3072][192]
            const float* __restrict__ bias,        // b2 [3072]
            const float* __restrict__ xres,
            const float* __restrict__ gate,
            float* __restrict__ out) {
    __shared__ __nv_bfloat16 sA[64][104];   // 64 rows x 96 cols (+8 pad)
    __shared__ __nv_bfloat16 sB[64][104];
    int tid = threadIdx.x, wid = tid >> 5, lane = tid & 31;
    int bm = blockIdx.y * 64, bn = blockIdx.x * 64;
    int wm = (wid & 1) * 32, wn = (wid >> 1) * 32;

    float c[2][4][4];
#pragma unroll
    for (int i = 0; i < 2; i++)
#pragma unroll
        for (int j = 0; j < 4; j++)
#pragma unroll
            for (int q = 0; q < 4; q++) c[i][j][q] = 0.f;

#pragma unroll
    for (int p = 0; p < 2; p++) {
        // stage 64x96 of A and B (768 16B-chunks each; 6 per thread per tile)
#pragma unroll
        for (int t = 0; t < 6; t++) {
            int i = tid + t * 128;
            int row = i / 12, ch = (i % 12) * 8;
            CP_ASYNC16(s2u(&sA[row][ch]), A + (size_t)(bm + row) * C_ + p * 96 + ch);
            CP_ASYNC16(s2u(&sB[row][ch]), Bm + (size_t)(bn + row) * C_ + p * 96 + ch);
        }
        CP_COMMIT();
        CP_WAIT(0);
        __syncthreads();
#pragma unroll
        for (int ks = 0; ks < 6; ks++) {
            int kk = ks * 16;
            uint32_t a[2][4], b[4][2];
#pragma unroll
            for (int mi = 0; mi < 2; mi++) {
                uint32_t addr = s2u(&sA[wm + mi * 16 + (lane & 15)][kk + (lane >> 4) * 8]);
                asm volatile("ldmatrix.sync.aligned.m8n8.x4.shared.b16 {%0,%1,%2,%3}, [%4];"
                             : "=r"(a[mi][0]), "=r"(a[mi][1]), "=r"(a[mi][2]), "=r"(a[mi][3])
                             : "r"(addr));
            }
#pragma unroll
            for (int ni = 0; ni < 4; ni++) {
                int l = lane & 15;
                uint32_t addr = s2u(&sB[wn + ni * 8 + (l & 7)][kk + (l >> 3) * 8]);
                asm volatile("ldmatrix.sync.aligned.m8n8.x2.shared.b16 {%0,%1}, [%2];"
                             : "=r"(b[ni][0]), "=r"(b[ni][1]) : "r"(addr));
            }
#pragma unroll
            for (int mi = 0; mi < 2; mi++)
#pragma unroll
                for (int ni = 0; ni < 4; ni++)
                    asm volatile(
                        "mma.sync.aligned.m16n8k16.row.col.f32.bf16.bf16.f32 "
                        "{%0,%1,%2,%3}, {%4,%5,%6,%7}, {%8,%9}, {%0,%1,%2,%3};"
                        : "+f"(c[mi][ni][0]), "+f"(c[mi][ni][1]),
                          "+f"(c[mi][ni][2]), "+f"(c[mi][ni][3])
                        : "r"(a[mi][0]), "r"(a[mi][1]), "r"(a[mi][2]), "r"(a[mi][3]),
                          "r"(b[ni][0]), "r"(b[ni][1]));
        }
        __syncthreads();   // protect smem reuse for phase 1
    }

    // fused final epilogue: window reverse + roll(+2,+2) + gate blend + residual
    float g = sigmoidf_(gate[0]);
#pragma unroll
    for (int mi = 0; mi < 2; mi++) {
        int row0 = bm + wm + mi * 16 + (lane >> 2);
#pragma unroll
        for (int rr = 0; rr < 2; rr++) {
            int row = row0 + rr * 8;           // window index
            if (row >= BW) continue;
            int b   = row / (NWH * NWH);
            int r2  = row % (NWH * NWH);
            int wh  = r2 / NWH, ww = r2 % NWH;
#pragma unroll
            for (int ni = 0; ni < 4; ni++) {
                int col = bn + wn + ni * 8 + (lane & 3) * 2;
                int wpos = col / C_;
                int ch   = col - wpos * C_;
                int hr = wh * 4 + (wpos >> 2);
                int wr = ww * 4 + (wpos & 3);
                int h = hr + 2; if (h >= H_) h -= H_;
                int w = wr + 2; if (w >= W_) w -= W_;
                size_t pix = ((size_t)(b * H_ + h) * W_ + w) * C_ + ch;
                float v0 = c[mi][ni][rr * 2 + 0];
                float v1 = c[mi][ni][rr * 2 + 1];
                float m0 = sigmoidf_(v0 + bias[col]);
                float m1 = sigmoidf_(v1 + bias[col + 1]);
                float2 xv = *(const float2*)(xres + pix);
                float2 o;
                o.x = xv.x + g * m0 + (1.0f - g) * sigmoidf_(m0);
                o.y = xv.y + g * m1 + (1.0f - g) * sigmoidf_(m1);
                *(float2*)(out + pix) = o;
            }
        }
    }
}

// ------- fused: combine split-K -> clause bits -> outputs -> sparse logits -----
// logits[w,n] = (1/16) * sum over active clauses of vote_w[cl][n]
__global__ void combine_clause_kernel(const float* __restrict__ b1,
                                      const float* __restrict__ vote_w,
                                      float* __restrict__ out_cl,
                                      float* __restrict__ out_sum) {
    __shared__ uint32_t slit[16];
    __shared__ int      swbase[8];
    __shared__ int      scount;
    __shared__ uint16_t sact[256];
    int row  = blockIdx.x;       // 0..MP-1
    int c    = threadIdx.x;      // 0..255  (feature, then clause)
    int wid  = c >> 5, lane = c & 31;
    if (c == 0) scount = 0;
    float s = b1[c];
#pragma unroll
    for (int z = 0; z < KSPL; z++) s += g_part[(size_t)z * MP * HID + (size_t)row * HID + c];
    uint32_t mp = __ballot_sync(0xffffffffu, s > 0.0f);
    uint32_t mn = __ballot_sync(0xffffffffu, s < 0.0f);
    if ((c & 31) == 0) {
        slit[c >> 5]       = mp;
        slit[8 + (c >> 5)] = mn;
    }
    __syncthreads();
    uint32_t viol = 0;
#pragma unroll
    for (int i = 0; i < 16; i++) viol |= g_incb[i * NCL + c] & ~slit[i];
    bool act = (viol == 0u);
    if (row < BW) out_cl[(size_t)row * NCL + c] = act ? 1.0f : 0.0f;
    // compact active clause indices into sact[]
    uint32_t cm = __ballot_sync(0xffffffffu, act);
    if (lane == 0) swbase[wid] = atomicAdd(&scount, __popc(cm));
    __syncwarp();
    if (act) {
        int pos = swbase[wid] + __popc(cm & ((1u << lane) - 1u));
        sact[pos] = (uint16_t)c;
    }
    __syncthreads();
    int total = scount;
    if (c == 0 && row < BW) out_sum[row] = (float)total * (1.0f / NCL);
    // sparse logits: sum active vote_w rows (coalesced across n)
    if (c < C_) {
        float acc = 0.f;
        for (int i = 0; i < total; i++)
            acc += vote_w[(size_t)sact[i] * C_ + c];
        g_logb[(size_t)row * C_ + c] = __float2bfloat16_rn(acc * 0.0625f);
    }
}

// ---------------- host launcher -----------------------------------------------
static void* sym_addr(const void* sym) {
    void* p = nullptr;
    cudaGetSymbolAddress(&p, sym);
    return p;
}

extern "C" void kernel_launch(void* const* d_in, const int* in_sizes, int n_in,
                              void* d_out, int out_size) {
    const float* x      = (const float*)d_in[0];
    const float* gamma  = (const float*)d_in[1];
    const float* beta   = (const float*)d_in[2];
    const float* W1     = (const float*)d_in[3];
    const float* b1     = (const float*)d_in[4];
    const float* inc_w  = (const float*)d_in[5];
    const float* vote_w = (const float*)d_in[6];
    const float* W2     = (const float*)d_in[7];
    const float* b2     = (const float*)d_in[8];
    const float* gate   = (const float*)d_in[9];

    float* out     = (float*)d_out;
    float* out_cl  = out + (size_t)B_ * H_ * W_ * C_;
    float* out_sum = out_cl + (size_t)BW * NCL;

    __nv_bfloat16* p_win  = (__nv_bfloat16*)sym_addr(g_win);
    __nv_bfloat16* p_W1T  = (__nv_bfloat16*)sym_addr(g_W1T);
    __nv_bfloat16* p_W2T  = (__nv_bfloat16*)sym_addr(g_W2T);
    __nv_bfloat16* p_logb = (__nv_bfloat16*)sym_addr(g_logb);
    float*         p_part = (float*)sym_addr(g_part);

    // 1) fused: LN + roll + partition  AND  weight transposes + include bitpack
    ln_prep_kernel<<<NB_LN + NB_PREP, 256>>>(x, gamma, beta, W1, W2, inc_w);
    // 2) GEMM1 (split-K=4): partials = win @ W1
    mma_gemm1<<<dim3(2, 13, KSPL), 256>>>(p_win, IND, p_W1T, IND,
                                          p_part, HID, IND / KSPL, MP * HID);
    // 3) combine partials -> clause bits + outputs + sparse logits
    combine_clause_kernel<<<MP, 256>>>(b1, vote_w, out_cl, out_sum);
    // 4) GEMM3 (64x64 tiles, full-K) + fused final epilogue
    gemm3_final<<<dim3(48, 26), 128>>>(p_logb, p_W2T, b2, x, gate, out);
}

// round 16
// speedup vs baseline: 1.3311x; 1.1134x over previous
#include <cuda_runtime.h>
#include <cuda_bf16.h>
#include <cstdint>

// ---------------- problem constants ----------------
#define B_    8
#define H_    56
#define W_    56
#define C_    192
#define NWH   14            // windows per side (56/4)
#define BW    1568          // total windows
#define MP    1664          // padded window rows = 13 * 128
#define IND   3072          // 4*4*192
#define HID   256
#define NCL   256
#define KSPL  4             // GEMM1 split-K

// ---------------- scratch (__device__ globals, zero-initialized) ----------
__device__ __nv_bfloat16 g_win[MP * IND];        // LN'd windows, bf16
__device__ __nv_bfloat16 g_W1T[HID * IND];       // W1^T  [256][3072]
__device__ __nv_bfloat16 g_W2T[IND * C_];        // W2^T  [3072][192]
__device__ __nv_bfloat16 g_vwb[NCL * C_];        // vote_w bf16 [256][192]
__device__ float         g_V[NCL * IND];         // V = (vote_w @ W2)/16  [256][3072]
__device__ float         g_part[KSPL * MP * HID];// GEMM1 split-K partials
__device__ uint32_t      g_incb[16 * NCL];       // include bits [16 words][256 clauses]
__device__ uint16_t      g_act[MP * NCL];        // active clause indices per window
__device__ int           g_cnt[MP];              // active clause count per window

__device__ __forceinline__ float sigmoidf_(float x) { return 1.0f / (1.0f + __expf(-x)); }

__device__ __forceinline__ uint32_t s2u(const void* p) {
    uint32_t a;
    asm("{ .reg .u64 t; cvta.to.shared.u64 t, %1; cvt.u32.u64 %0, t; }" : "=r"(a) : "l"(p));
    return a;
}
#define CP_ASYNC16(dst, src) \
    asm volatile("cp.async.cg.shared.global [%0], [%1], 16;" :: "r"(dst), "l"(src))
#define CP_COMMIT() asm volatile("cp.async.commit_group;")
#define CP_WAIT(n)  asm volatile("cp.async.wait_group %0;" :: "n"(n))

// ---------------- fused K1: LN+roll+partition  AND  weight prep ---------------
#define NB_LN   3136           // 25088 pixels / 8 warps
#define SEG1 786432            // trW1:  3072*256
#define SEG2 1376256           // +trW2: 192*3072
#define SEG3 1507328           // +pack_inc: 256*512
#define SEGT 1556480           // +vote_w bf16 copy: 256*192
#define NB_PREP (SEGT / 256)   // 6080
__global__ void ln_prep_kernel(const float* __restrict__ x,
                               const float* __restrict__ gamma,
                               const float* __restrict__ beta,
                               const float* __restrict__ W1,
                               const float* __restrict__ W2,
                               const float* __restrict__ inc_w,
                               const float* __restrict__ vw) {
    if (blockIdx.x < NB_LN) {
        int gwarp = (blockIdx.x * blockDim.x + threadIdx.x) >> 5;
        int lane  = threadIdx.x & 31;
        const float* xr = x + (size_t)gwarp * C_;
        float v[6];
        float s = 0.f, ss = 0.f;
#pragma unroll
        for (int k = 0; k < 6; k++) {
            v[k] = xr[lane + 32 * k];
            s += v[k]; ss += v[k] * v[k];
        }
#pragma unroll
        for (int o = 16; o > 0; o >>= 1) {
            s  += __shfl_xor_sync(0xffffffffu, s, o);
            ss += __shfl_xor_sync(0xffffffffu, ss, o);
        }
        float mean = s * (1.0f / C_);
        float var  = ss * (1.0f / C_) - mean * mean;
        float inv  = rsqrtf(var + 1e-5f);

        int p = gwarp;
        int w = p % W_;
        int h = (p / W_) % H_;
        int b = p / (H_ * W_);
        int hr = (h + H_ - 2) % H_;
        int wr = (w + W_ - 2) % W_;
        int row  = b * (NWH * NWH) + (hr >> 2) * NWH + (wr >> 2);
        size_t base = (size_t)row * IND + ((hr & 3) * 4 + (wr & 3)) * C_;
#pragma unroll
        for (int k = 0; k < 6; k++) {
            int c = lane + 32 * k;
            g_win[base + c] = __float2bfloat16_rn((v[k] - mean) * inv * gamma[c] + beta[c]);
        }
    } else {
        int t = (blockIdx.x - NB_LN) * blockDim.x + threadIdx.x;
        if (t < SEG1) {                       // [3072][256] -> [256][3072]
            int k = t >> 8, n = t & 255;
            g_W1T[(size_t)n * IND + k] = __float2bfloat16_rn(W1[t]);
        } else if (t < SEG2) {                // [192][3072] -> [3072][192]
            int u = t - SEG1;
            int k = u / IND, n = u % IND;
            g_W2T[(size_t)n * C_ + k] = __float2bfloat16_rn(W2[u]);
        } else if (t < SEG3) {                // include bits: inc = (inc_w > 0)
            int u  = t - SEG2;
            int cl = u >> 9, j = u & 511;
            bool v = inc_w[(size_t)cl * 512 + j] > 0.0f;
            uint32_t m = __ballot_sync(0xffffffffu, v);
            if ((j & 31) == 0) g_incb[(j >> 5) * NCL + cl] = m;
        } else {                              // vote_w fp32 -> bf16 (same layout)
            int u = t - SEG3;
            g_vwb[u] = __float2bfloat16_rn(vw[u]);
        }
    }
}

// ---------------- bf16 mma.sync GEMM, 128x128 tile, 2-stage cp.async ----------
// Cf[m][n] = scale * sum_k A[m][k]*B[n][k]   (+ z*zStride offset for split-K)
__global__ void __launch_bounds__(256)
mma_gemm1(const __nv_bfloat16* __restrict__ A, int lda,
          const __nv_bfloat16* __restrict__ Bm, int ldb,
          float* __restrict__ Cf, int ldc, int kPerZ, int zStride, float scale) {
    __shared__ __nv_bfloat16 sA[2][128][40];
    __shared__ __nv_bfloat16 sB[2][128][40];
    int tid = threadIdx.x, wid = tid >> 5, lane = tid & 31;
    int bm = blockIdx.y * 128, bn = blockIdx.x * 128;
    int k0 = blockIdx.z * kPerZ;
    Cf += (size_t)blockIdx.z * zStride;

    int wm = (wid & 1) * 64;
    int wn = (wid >> 1) * 32;

    int i0 = tid,        r0 = i0 >> 2, c0 = (i0 & 3) * 8;
    int i1 = tid + 256,  r1 = i1 >> 2, c1 = (i1 & 3) * 8;
    const __nv_bfloat16* pA0 = A + (size_t)(bm + r0) * lda + c0;
    const __nv_bfloat16* pA1 = A + (size_t)(bm + r1) * lda + c1;
    const __nv_bfloat16* pB0 = Bm + (size_t)(bn + r0) * ldb + c0;
    const __nv_bfloat16* pB1 = Bm + (size_t)(bn + r1) * ldb + c1;

    float c[4][4][4];
#pragma unroll
    for (int i = 0; i < 4; i++)
#pragma unroll
        for (int j = 0; j < 4; j++)
#pragma unroll
            for (int q = 0; q < 4; q++) c[i][j][q] = 0.f;

    int iters = kPerZ >> 5;
    CP_ASYNC16(s2u(&sA[0][r0][c0]), pA0 + k0);
    CP_ASYNC16(s2u(&sA[0][r1][c1]), pA1 + k0);
    CP_ASYNC16(s2u(&sB[0][r0][c0]), pB0 + k0);
    CP_ASYNC16(s2u(&sB[0][r1][c1]), pB1 + k0);
    CP_COMMIT();

    for (int it = 0; it < iters; ++it) {
        if (it + 1 < iters) {
            int s = (it + 1) & 1;
            int kb = k0 + (it + 1) * 32;
            CP_ASYNC16(s2u(&sA[s][r0][c0]), pA0 + kb);
            CP_ASYNC16(s2u(&sA[s][r1][c1]), pA1 + kb);
            CP_ASYNC16(s2u(&sB[s][r0][c0]), pB0 + kb);
            CP_ASYNC16(s2u(&sB[s][r1][c1]), pB1 + kb);
            CP_COMMIT();
            CP_WAIT(1);
        } else {
            CP_WAIT(0);
        }
        __syncthreads();
        int cs = it & 1;
#pragma unroll
        for (int ks = 0; ks < 2; ks++) {
            int kk = ks * 16;
            uint32_t a[4][4], b[4][2];
#pragma unroll
            for (int mi = 0; mi < 4; mi++) {
                uint32_t addr = s2u(&sA[cs][wm + mi * 16 + (lane & 15)][kk + (lane >> 4) * 8]);
                asm volatile("ldmatrix.sync.aligned.m8n8.x4.shared.b16 {%0,%1,%2,%3}, [%4];"
                             : "=r"(a[mi][0]), "=r"(a[mi][1]), "=r"(a[mi][2]), "=r"(a[mi][3])
                             : "r"(addr));
            }
#pragma unroll
            for (int ni = 0; ni < 4; ni++) {
                int l = lane & 15;
                uint32_t addr = s2u(&sB[cs][wn + ni * 8 + (l & 7)][kk + (l >> 3) * 8]);
                asm volatile("ldmatrix.sync.aligned.m8n8.x2.shared.b16 {%0,%1}, [%2];"
                             : "=r"(b[ni][0]), "=r"(b[ni][1]) : "r"(addr));
            }
#pragma unroll
            for (int mi = 0; mi < 4; mi++)
#pragma unroll
                for (int ni = 0; ni < 4; ni++)
                    asm volatile(
                        "mma.sync.aligned.m16n8k16.row.col.f32.bf16.bf16.f32 "
                        "{%0,%1,%2,%3}, {%4,%5,%6,%7}, {%8,%9}, {%0,%1,%2,%3};"
                        : "+f"(c[mi][ni][0]), "+f"(c[mi][ni][1]),
                          "+f"(c[mi][ni][2]), "+f"(c[mi][ni][3])
                        : "r"(a[mi][0]), "r"(a[mi][1]), "r"(a[mi][2]), "r"(a[mi][3]),
                          "r"(b[ni][0]), "r"(b[ni][1]));
        }
        __syncthreads();
    }

#pragma unroll
    for (int mi = 0; mi < 4; mi++) {
        int row = bm + wm + mi * 16 + (lane >> 2);
#pragma unroll
        for (int ni = 0; ni < 4; ni++) {
            int col = bn + wn + ni * 8 + (lane & 3) * 2;
            *(float2*)(Cf + (size_t)row * ldc + col) =
                make_float2(c[mi][ni][0] * scale, c[mi][ni][1] * scale);
            *(float2*)(Cf + (size_t)(row + 8) * ldc + col) =
                make_float2(c[mi][ni][2] * scale, c[mi][ni][3] * scale);
        }
    }
}

// ------- fused: combine split-K -> clause bits -> outputs -> active list -------
__global__ void combine_clause_kernel(const float* __restrict__ b1,
                                      float* __restrict__ out_cl,
                                      float* __restrict__ out_sum) {
    __shared__ uint32_t slit[16];
    __shared__ int      swbase[8];
    __shared__ int      scount;
    int row  = blockIdx.x;       // 0..MP-1
    int c    = threadIdx.x;      // 0..255  (feature, then clause)
    int wid  = c >> 5, lane = c & 31;
    if (c == 0) scount = 0;
    float s = b1[c];
#pragma unroll
    for (int z = 0; z < KSPL; z++) s += g_part[(size_t)z * MP * HID + (size_t)row * HID + c];
    uint32_t mp = __ballot_sync(0xffffffffu, s > 0.0f);
    uint32_t mn = __ballot_sync(0xffffffffu, s < 0.0f);
    if ((c & 31) == 0) {
        slit[c >> 5]       = mp;
        slit[8 + (c >> 5)] = mn;
    }
    __syncthreads();
    uint32_t viol = 0;
#pragma unroll
    for (int i = 0; i < 16; i++) viol |= g_incb[i * NCL + c] & ~slit[i];
    bool act = (viol == 0u);
    if (row < BW) out_cl[(size_t)row * NCL + c] = act ? 1.0f : 0.0f;
    // compact active clause indices to global
    uint32_t cm = __ballot_sync(0xffffffffu, act);
    if (lane == 0) swbase[wid] = atomicAdd(&scount, __popc(cm));
    __syncwarp();
    if (act) {
        int pos = swbase[wid] + __popc(cm & ((1u << lane) - 1u));
        g_act[row * NCL + pos] = (uint16_t)c;
    }
    __syncthreads();
    int total = scount;
    if (c == 0) {
        g_cnt[row] = total;
        if (row < BW) out_sum[row] = (float)total * (1.0f / NCL);
    }
}

// ------- final: sparse V row-sum + sigmoid + window reverse + gate + residual ---
// one block per window (1568); 256 threads cover 3072 values (12 each)
__global__ void __launch_bounds__(256)
final_kernel(const float* __restrict__ b2,
             const float* __restrict__ xres,
             const float* __restrict__ gate,
             float* __restrict__ out) {
    __shared__ uint16_t sact[NCL];
    int row = blockIdx.x;        // window index 0..BW-1
    int tid = threadIdx.x;
    int cnt = g_cnt[row];
    for (int i = tid; i < cnt; i += 256) sact[i] = g_act[row * NCL + i];
    __syncthreads();

    int b  = row / (NWH * NWH);
    int r2 = row % (NWH * NWH);
    int wh = r2 / NWH, ww = r2 % NWH;
    float g = sigmoidf_(gate[0]);

#pragma unroll
    for (int j = 0; j < 12; j++) {
        int v    = tid + j * 256;        // 0..3071 = wpos*192 + ch
        int wpos = v / C_;
        int ch   = v - wpos * C_;
        float acc = b2[v];
        for (int i = 0; i < cnt; i++)
            acc += g_V[(size_t)sact[i] * IND + v];
        float m = sigmoidf_(acc);
        int hr = wh * 4 + (wpos >> 2);
        int wr = ww * 4 + (wpos & 3);
        int h = hr + 2; if (h >= H_) h -= H_;
        int w = wr + 2; if (w >= W_) w -= W_;
        size_t pix = ((size_t)(b * H_ + h) * W_ + w) * C_ + ch;
        out[pix] = xres[pix] + g * m + (1.0f - g) * sigmoidf_(m);
    }
}

// ---------------- host launcher -----------------------------------------------
static void* sym_addr(const void* sym) {
    void* p = nullptr;
    cudaGetSymbolAddress(&p, sym);
    return p;
}

extern "C" void kernel_launch(void* const* d_in, const int* in_sizes, int n_in,
                              void* d_out, int out_size) {
    const float* x      = (const float*)d_in[0];
    const float* gamma  = (const float*)d_in[1];
    const float* beta   = (const float*)d_in[2];
    const float* W1     = (const float*)d_in[3];
    const float* b1     = (const float*)d_in[4];
    const float* inc_w  = (const float*)d_in[5];
    const float* vote_w = (const float*)d_in[6];
    const float* W2     = (const float*)d_in[7];
    const float* b2     = (const float*)d_in[8];
    const float* gate   = (const float*)d_in[9];

    float* out     = (float*)d_out;
    float* out_cl  = out + (size_t)B_ * H_ * W_ * C_;
    float* out_sum = out_cl + (size_t)BW * NCL;

    __nv_bfloat16* p_win  = (__nv_bfloat16*)sym_addr(g_win);
    __nv_bfloat16* p_W1T  = (__nv_bfloat16*)sym_addr(g_W1T);
    __nv_bfloat16* p_W2T  = (__nv_bfloat16*)sym_addr(g_W2T);
    __nv_bfloat16* p_vwb  = (__nv_bfloat16*)sym_addr(g_vwb);
    float*         p_V    = (float*)sym_addr(g_V);
    float*         p_part = (float*)sym_addr(g_part);

    // 1) fused: LN + roll + partition  AND  weight transposes + bitpack + vote bf16
    ln_prep_kernel<<<NB_LN + NB_PREP, 256>>>(x, gamma, beta, W1, W2, inc_w, vote_w);
    // 2a) V = (vote_w @ W2) / 16   (M=256, N=3072, K=192)
    mma_gemm1<<<dim3(24, 2, 1), 256>>>(p_vwb, C_, p_W2T, C_, p_V, IND, C_, 0, 0.0625f);
    // 2b) GEMM1 (split-K=4): partials = win @ W1
    mma_gemm1<<<dim3(2, 13, KSPL), 256>>>(p_win, IND, p_W1T, IND,
                                          p_part, HID, IND / KSPL, MP * HID, 1.0f);
    // 3) combine partials -> clause bits + outputs + active-clause list
    combine_clause_kernel<<<MP, 256>>>(b1, out_cl, out_sum);
    // 4) final: sparse V sum + sigmoid + window reverse + roll + gate + residual
    final_kernel<<<BW, 256>>>(b2, x, gate, out);
}